// round 1
// baseline (speedup 1.0000x reference)
#include <cuda_runtime.h>

// Problem constants (DeepFM_10368051052905)
#define BQ      16384     // batch
#define NCQ     13        // continuous features
#define FQ      26        // categorical features
#define VQ      100000    // vocab
#define DQ      16        // embedding dim
#define H1Q     400
#define H2Q     400
#define DNN_INQ 429       // NC + F*D

// ---------------------------------------------------------------------------
// Scratch (static device globals — no runtime allocation)
// ---------------------------------------------------------------------------
__device__ float g_dnn[BQ * DNN_INQ];   // [B, 429] = [continuous | E]
__device__ float g_h1 [BQ * H1Q];       // [B, 400]
__device__ float g_h2 [BQ * H2Q];       // [B, 400]
__device__ float g_fm [BQ];             // fm1 + fm2 per row

// ---------------------------------------------------------------------------
// Kernel 1: embedding gather + FM (1st + 2nd order) + build dnn_in
// One warp per row. Lanes 0..15 own embedding dim d; lanes 0..25 own
// emb_first gathers; lanes 0..12 own the continuous part.
// ---------------------------------------------------------------------------
__global__ void gather_fm_kernel(const float* __restrict__ cont,
                                 const int*   __restrict__ cat,
                                 const float* __restrict__ Wc,
                                 const float* __restrict__ bc,
                                 const float* __restrict__ emb1,
                                 const float* __restrict__ emb)
{
    int row  = blockIdx.x * blockDim.y + threadIdx.y;
    int lane = threadIdx.x;
    if (row >= BQ) return;

    const int* idx = cat + row * FQ;
    float acc = 0.f;

    if (lane < DQ) {
        float s = 0.f, ss = 0.f;
        #pragma unroll
        for (int f = 0; f < FQ; f++) {
            int id  = idx[f];                               // broadcast load
            float e = emb[((long)f * VQ + id) * DQ + lane]; // gathered 64B row
            g_dnn[row * DNN_INQ + NCQ + f * DQ + lane] = e;
            s  += e;
            ss += e * e;
        }
        acc += 0.5f * (s * s - ss);   // per-dim FM2 contribution
    }
    if (lane < FQ) {
        int id = idx[lane];
        acc += emb1[(long)lane * VQ + id];                  // FM1 categorical
    }
    if (lane < NCQ) {
        float c = cont[row * NCQ + lane];
        g_dnn[row * DNN_INQ + lane] = c;
        acc += c * Wc[lane];                                // FM1 continuous
    }

    #pragma unroll
    for (int o = 16; o > 0; o >>= 1)
        acc += __shfl_down_sync(0xffffffffu, acc, o);
    if (lane == 0) g_fm[row] = acc + bc[0];
}

// ---------------------------------------------------------------------------
// Kernel 2/3: tiled fp32 GEMM + bias + ReLU
//   C[M,N] = relu(A[M,K] * W[K,N] + bias[N]),  M = BQ
// 128x64 block tile, BK=16, 256 threads, 8x4 microtile per thread.
// FMA-issue-bound by construction (256 warp-FMA vs 96 warp-LDS per k-step).
// ---------------------------------------------------------------------------
#define GBM 128
#define GBN 64
#define GBK 16
#define GTM 8
#define GTN 4

__global__ __launch_bounds__(256)
void gemm_bias_relu_kernel(const float* __restrict__ A,
                           const float* __restrict__ W,
                           const float* __restrict__ bias,
                           float* __restrict__ C,
                           int K, int N)
{
    __shared__ float As[GBM][GBK + 1];   // +1 pad: conflict-free stores
    __shared__ float Bs[GBK][GBN];

    int t    = threadIdx.x;
    int tx   = t & 15;          // n direction (16 * 4 = 64)
    int ty   = t >> 4;          // m direction (16 * 8 = 128)
    int row0 = blockIdx.y * GBM;
    int n0   = blockIdx.x * GBN;

    float acc[GTM][GTN];
    #pragma unroll
    for (int i = 0; i < GTM; i++)
        #pragma unroll
        for (int j = 0; j < GTN; j++)
            acc[i][j] = 0.f;

    for (int k0 = 0; k0 < K; k0 += GBK) {
        // A tile: 128x16, 8 elements per thread, coalesced along k
        #pragma unroll
        for (int i = 0; i < (GBM * GBK) / 256; i++) {
            int e = t + i * 256;
            int m = e >> 4, k = e & 15;
            float v = 0.f;
            if (k0 + k < K) v = A[(long)(row0 + m) * K + k0 + k];
            As[m][k] = v;
        }
        // B tile: 16x64, 4 elements per thread, coalesced along n
        #pragma unroll
        for (int i = 0; i < (GBK * GBN) / 256; i++) {
            int e = t + i * 256;
            int k = e >> 6, n = e & 63;
            float v = 0.f;
            if (k0 + k < K && n0 + n < N) v = W[(long)(k0 + k) * N + n0 + n];
            Bs[k][n] = v;
        }
        __syncthreads();

        #pragma unroll
        for (int k = 0; k < GBK; k++) {
            float a[GTM], b[GTN];
            #pragma unroll
            for (int i = 0; i < GTM; i++) a[i] = As[ty * GTM + i][k];
            #pragma unroll
            for (int j = 0; j < GTN; j++) b[j] = Bs[k][tx * GTN + j];
            #pragma unroll
            for (int i = 0; i < GTM; i++)
                #pragma unroll
                for (int j = 0; j < GTN; j++)
                    acc[i][j] += a[i] * b[j];
        }
        __syncthreads();
    }

    #pragma unroll
    for (int i = 0; i < GTM; i++) {
        int r = row0 + ty * GTM + i;    // M = 16384 divisible by 128: no guard
        #pragma unroll
        for (int j = 0; j < GTN; j++) {
            int c = n0 + tx * GTN + j;
            if (c < N) {
                float v = acc[i][j] + bias[c];
                C[(long)r * N + c] = v > 0.f ? v : 0.f;
            }
        }
    }
}

// ---------------------------------------------------------------------------
// Kernel 4: out = fm_out * W_out[0] + h2 . W_out[1:401] + b_out
// One warp per row.
// ---------------------------------------------------------------------------
__global__ void out_kernel(const float* __restrict__ Wout,
                           const float* __restrict__ bout,
                           float* __restrict__ out)
{
    int row  = blockIdx.x * blockDim.y + threadIdx.y;
    int lane = threadIdx.x;
    if (row >= BQ) return;

    float acc = 0.f;
    const float* h2row = g_h2 + (long)row * H2Q;
    for (int j = lane; j < H2Q; j += 32)
        acc += h2row[j] * Wout[1 + j];
    #pragma unroll
    for (int o = 16; o > 0; o >>= 1)
        acc += __shfl_down_sync(0xffffffffu, acc, o);
    if (lane == 0)
        out[row] = g_fm[row] * Wout[0] + acc + bout[0];
}

// ---------------------------------------------------------------------------
// Launch
// ---------------------------------------------------------------------------
extern "C" void kernel_launch(void* const* d_in, const int* in_sizes, int n_in,
                              void* d_out, int out_size)
{
    const float* cont = (const float*)d_in[0];
    const int*   cat  = (const int*)  d_in[1];
    const float* Wc   = (const float*)d_in[2];
    const float* bc   = (const float*)d_in[3];
    const float* emb1 = (const float*)d_in[4];
    const float* emb  = (const float*)d_in[5];
    const float* W1   = (const float*)d_in[6];
    const float* b1   = (const float*)d_in[7];
    const float* W2   = (const float*)d_in[8];
    const float* b2   = (const float*)d_in[9];
    const float* Wout = (const float*)d_in[10];
    const float* bout = (const float*)d_in[11];
    float* out = (float*)d_out;

    void *p_dnn, *p_h1, *p_h2;
    cudaGetSymbolAddress(&p_dnn, g_dnn);
    cudaGetSymbolAddress(&p_h1,  g_h1);
    cudaGetSymbolAddress(&p_h2,  g_h2);
    float* dnn = (float*)p_dnn;
    float* h1  = (float*)p_h1;
    float* h2  = (float*)p_h2;

    // 1) gather + FM + build dnn_in
    {
        dim3 blk(32, 8);
        dim3 grd(BQ / 8);
        gather_fm_kernel<<<grd, blk>>>(cont, cat, Wc, bc, emb1, emb);
    }
    // 2) h1 = relu(dnn_in @ W1 + b1)   [16384 x 429] @ [429 x 400]
    {
        dim3 grd((H1Q + GBN - 1) / GBN, BQ / GBM);   // (7, 128)
        gemm_bias_relu_kernel<<<grd, 256>>>(dnn, W1, b1, h1, DNN_INQ, H1Q);
    }
    // 3) h2 = relu(h1 @ W2 + b2)       [16384 x 400] @ [400 x 400]
    {
        dim3 grd((H2Q + GBN - 1) / GBN, BQ / GBM);
        gemm_bias_relu_kernel<<<grd, 256>>>(h1, W2, b2, h2, H1Q, H2Q);
    }
    // 4) out = [fm_out, h2] @ W_out + b_out
    {
        dim3 blk(32, 8);
        dim3 grd(BQ / 8);
        out_kernel<<<grd, blk>>>(Wout, bout, out);
    }
}

// round 3
// speedup vs baseline: 2.0960x; 2.0960x over previous
#include <cuda_runtime.h>
#include <cuda_bf16.h>
#include <cstdint>

// ---------------- problem constants ----------------
#define BQ      16384
#define NCQ     13
#define FQ      26
#define VQ      100000
#define DQ      16
#define HQ      400       // H1 == H2
#define DNN_INQ 429
#define KP      448       // padded K (14 * 32)
#define NPAD    448       // padded N for transposed weights (7 * 64)

// GEMM tiling
#define BM 128
#define BN 64
#define BK 32
#define NIT (KP / BK)     // 14
#define AST 80            // smem row stride bytes (64B data + 16B pad, conflict-free)

// smem stage layout (bytes)
#define A_HI_OFF 0
#define A_LO_OFF 10240    // 128 * 80
#define B_HI_OFF 20480
#define B_LO_OFF 25600    // + 64 * 80
#define STAGE    30720
#define SMEM_TOTAL (2 * STAGE)

// ---------------- scratch (static device globals) ----------------
__device__ __align__(16) __nv_bfloat16 g_dnn_hi[BQ * KP];
__device__ __align__(16) __nv_bfloat16 g_dnn_lo[BQ * KP];
__device__ __align__(16) __nv_bfloat16 g_h1_hi [BQ * KP];
__device__ __align__(16) __nv_bfloat16 g_h1_lo [BQ * KP];
__device__ __align__(16) float         g_h2    [BQ * HQ];
__device__ float                       g_fm    [BQ];
__device__ __align__(16) __nv_bfloat16 g_w1t_hi[NPAD * KP];
__device__ __align__(16) __nv_bfloat16 g_w1t_lo[NPAD * KP];
__device__ __align__(16) __nv_bfloat16 g_w2t_hi[NPAD * KP];
__device__ __align__(16) __nv_bfloat16 g_w2t_lo[NPAD * KP];

// ---------------- PTX helpers (all sm_80-class, legal in compute_103) -------
__device__ __forceinline__ uint32_t smem_u32_of(const void* p) {
    uint32_t a;
    asm("{ .reg .u64 t; cvta.to.shared.u64 t, %1; cvt.u32.u64 %0, t; }" : "=r"(a) : "l"(p));
    return a;
}

#define LDMATRIX_X4(r, addr) \
    asm volatile("ldmatrix.sync.aligned.m8n8.x4.shared.b16 {%0,%1,%2,%3}, [%4];" \
                 : "=r"((r)[0]), "=r"((r)[1]), "=r"((r)[2]), "=r"((r)[3]) \
                 : "r"(addr))

#define MMA16816(d, a, b0, b1) \
    asm volatile("mma.sync.aligned.m16n8k16.row.col.f32.bf16.bf16.f32 " \
                 "{%0,%1,%2,%3}, {%4,%5,%6,%7}, {%8,%9}, {%0,%1,%2,%3};" \
                 : "+f"((d)[0]), "+f"((d)[1]), "+f"((d)[2]), "+f"((d)[3]) \
                 : "r"((a)[0]), "r"((a)[1]), "r"((a)[2]), "r"((a)[3]), \
                   "r"(b0), "r"(b1))

// ---------------------------------------------------------------------------
// Kernel 1: embedding gather + FM + build dnn_in (bf16 hi/lo split)
// One warp per row.
// ---------------------------------------------------------------------------
__global__ void gather_fm_kernel(const float* __restrict__ cont,
                                 const int*   __restrict__ cat,
                                 const float* __restrict__ Wc,
                                 const float* __restrict__ bc,
                                 const float* __restrict__ emb1,
                                 const float* __restrict__ emb)
{
    int row  = blockIdx.x * blockDim.y + threadIdx.y;
    int lane = threadIdx.x;
    if (row >= BQ) return;

    const int* idx = cat + row * FQ;
    long base = (long)row * KP;
    float acc = 0.f;

    if (lane < DQ) {
        float s = 0.f, ss = 0.f;
        #pragma unroll
        for (int f = 0; f < FQ; f++) {
            int id  = idx[f];
            float e = emb[((long)f * VQ + id) * DQ + lane];
            __nv_bfloat16 hi = __float2bfloat16(e);
            float lo = e - __bfloat162float(hi);
            int col = NCQ + f * DQ + lane;
            g_dnn_hi[base + col] = hi;
            g_dnn_lo[base + col] = __float2bfloat16(lo);
            s  += e;
            ss += e * e;
        }
        acc += 0.5f * (s * s - ss);
    }
    if (lane < FQ) {
        acc += emb1[(long)lane * VQ + idx[lane]];
    }
    if (lane < NCQ) {
        float c = cont[row * NCQ + lane];
        __nv_bfloat16 hi = __float2bfloat16(c);
        float lo = c - __bfloat162float(hi);
        g_dnn_hi[base + lane] = hi;
        g_dnn_lo[base + lane] = __float2bfloat16(lo);
        acc += c * Wc[lane];
    } else {
        int pc = DNN_INQ + (lane - NCQ);   // lanes 13..31 -> cols 429..447
        if (pc < KP) {
            g_dnn_hi[base + pc] = __float2bfloat16(0.f);
            g_dnn_lo[base + pc] = __float2bfloat16(0.f);
        }
    }

    #pragma unroll
    for (int o = 16; o > 0; o >>= 1)
        acc += __shfl_down_sync(0xffffffffu, acc, o);
    if (lane == 0) g_fm[row] = acc + bc[0];
}

// ---------------------------------------------------------------------------
// Prep: transpose + pad + split W [K][N] fp32 -> Wt hi/lo [NPAD][KP] bf16
// ---------------------------------------------------------------------------
__global__ void prep_w_kernel(const float* __restrict__ W,
                              __nv_bfloat16* __restrict__ Wh,
                              __nv_bfloat16* __restrict__ Wl,
                              int K, int N)
{
    int idx = blockIdx.x * blockDim.x + threadIdx.x;
    if (idx >= NPAD * KP) return;
    int n = idx / KP, k = idx % KP;
    float v = (k < K && n < N) ? W[(long)k * N + n] : 0.f;
    __nv_bfloat16 hi = __float2bfloat16(v);
    float lo = v - __bfloat162float(hi);
    Wh[idx] = hi;
    Wl[idx] = __float2bfloat16(lo);
}

// ---------------------------------------------------------------------------
// bf16x3 HMMA GEMM:  C[BQ, HQ] = relu(A * Wt^T + bias)
//   A (hi/lo): [BQ][KP] bf16 row-major; Wt (hi/lo): [NPAD][KP] bf16
// mode 0: write bf16 hi/lo (stride KP)  -> h1      (pad cols come out 0)
// mode 1: write fp32       (stride HQ)  -> h2
// ---------------------------------------------------------------------------
__global__ __launch_bounds__(256)
void gemm_mma_kernel(const __nv_bfloat16* __restrict__ Ah,
                     const __nv_bfloat16* __restrict__ Al,
                     const __nv_bfloat16* __restrict__ Bh,
                     const __nv_bfloat16* __restrict__ Bl,
                     const float* __restrict__ bias, int mode,
                     __nv_bfloat16* __restrict__ Ch,
                     __nv_bfloat16* __restrict__ Cl,
                     float* __restrict__ Cf)
{
    extern __shared__ __align__(16) char smem[];
    const uint32_t smem_b = smem_u32_of(smem);

    const int tid  = threadIdx.x;
    const int wid  = tid >> 5;
    const int lane = tid & 31;
    const int wm   = wid & 3;       // 4 warps along M (32 rows each)
    const int wn   = wid >> 2;      // 2 warps along N (32 cols each)

    const long row0 = (long)blockIdx.y * BM;
    const int  n0   = blockIdx.x * BN;

    // global load coords (per stage)
    const int ar = tid >> 2, ac = tid & 3;          // A: 2 uint4/thread/operand
    const int br = tid >> 2, bc_ = tid & 3;         // B: 1 uint4/thread/operand (tid<256 covers 64 rows x 4)
    const char* pAh = (const char*)Ah;
    const char* pAl = (const char*)Al;
    const char* pBh = (const char*)Bh;
    const char* pBl = (const char*)Bl;

    float acc[2][4][4];
    #pragma unroll
    for (int i = 0; i < 2; i++)
        #pragma unroll
        for (int j = 0; j < 4; j++)
            #pragma unroll
            for (int q = 0; q < 4; q++) acc[i][j][q] = 0.f;

    // ldmatrix base addresses (buf 0)
    const int arow = wm * 32 + (lane & 15);
    const int brow = wn * 32 + (lane & 15);
    const uint32_t halfoff = ((lane >> 4) & 1) * 16;
    const uint32_t aAddr0 = smem_b + A_HI_OFF + arow * AST + halfoff;
    const uint32_t bAddr0 = smem_b + B_HI_OFF + brow * AST + halfoff;

    // ---- preload stage 0 ----
    {
        const long kb = 0;
        #pragma unroll
        for (int i = 0; i < 2; i++) {
            int idx = tid + i * 256, r = idx >> 2, c = idx & 3;
            uint4 vh = *(const uint4*)(pAh + ((row0 + r) * KP + kb) * 2 + c * 16);
            uint4 vl = *(const uint4*)(pAl + ((row0 + r) * KP + kb) * 2 + c * 16);
            *(uint4*)(smem + A_HI_OFF + r * AST + c * 16) = vh;
            *(uint4*)(smem + A_LO_OFF + r * AST + c * 16) = vl;
        }
        {
            uint4 vh = *(const uint4*)(pBh + ((long)(n0 + br) * KP + kb) * 2 + bc_ * 16);
            uint4 vl = *(const uint4*)(pBl + ((long)(n0 + br) * KP + kb) * 2 + bc_ * 16);
            *(uint4*)(smem + B_HI_OFF + br * AST + bc_ * 16) = vh;
            *(uint4*)(smem + B_LO_OFF + br * AST + bc_ * 16) = vl;
        }
    }
    __syncthreads();

    for (int it = 0; it < NIT; ++it) {
        const int buf = it & 1;
        const bool more = (it + 1 < NIT);

        // prefetch next stage into registers
        uint4 nAh[2], nAl[2], nBh, nBl;
        if (more) {
            const long kb = (long)(it + 1) * BK;
            #pragma unroll
            for (int i = 0; i < 2; i++) {
                int idx = tid + i * 256, r = idx >> 2, c = idx & 3;
                nAh[i] = *(const uint4*)(pAh + ((row0 + r) * KP + kb) * 2 + c * 16);
                nAl[i] = *(const uint4*)(pAl + ((row0 + r) * KP + kb) * 2 + c * 16);
            }
            nBh = *(const uint4*)(pBh + ((long)(n0 + br) * KP + kb) * 2 + bc_ * 16);
            nBl = *(const uint4*)(pBl + ((long)(n0 + br) * KP + kb) * 2 + bc_ * 16);
        }

        // ---- compute on current buffer ----
        const uint32_t bufoff = buf ? STAGE : 0;
        #pragma unroll
        for (int kq = 0; kq < 2; kq++) {
            const uint32_t koff = bufoff + kq * 32;
            uint32_t ah[2][4], al[2][4], bh[2][4], bl[2][4];
            #pragma unroll
            for (int mt = 0; mt < 2; mt++) {
                LDMATRIX_X4(ah[mt], aAddr0 + koff + mt * (16 * AST));
                LDMATRIX_X4(al[mt], aAddr0 + koff + mt * (16 * AST) + (A_LO_OFF - A_HI_OFF));
            }
            #pragma unroll
            for (int g = 0; g < 2; g++) {
                LDMATRIX_X4(bh[g], bAddr0 + koff + g * (16 * AST));
                LDMATRIX_X4(bl[g], bAddr0 + koff + g * (16 * AST) + (B_LO_OFF - B_HI_OFF));
            }
            #pragma unroll
            for (int mt = 0; mt < 2; mt++) {
                #pragma unroll
                for (int g = 0; g < 2; g++) {
                    #pragma unroll
                    for (int s = 0; s < 2; s++) {
                        // ntile = g*2 + s ; frag regs (r_s, r_{s+2})
                        float* d = acc[mt][g * 2 + s];
                        MMA16816(d, ah[mt], bh[g][s], bh[g][s + 2]);
                        MMA16816(d, ah[mt], bl[g][s], bl[g][s + 2]);
                        MMA16816(d, al[mt], bh[g][s], bh[g][s + 2]);
                    }
                }
            }
        }

        // store prefetched stage
        if (more) {
            char* dst = smem + (buf ? 0 : STAGE);
            #pragma unroll
            for (int i = 0; i < 2; i++) {
                int idx = tid + i * 256, r = idx >> 2, c = idx & 3;
                *(uint4*)(dst + A_HI_OFF + r * AST + c * 16) = nAh[i];
                *(uint4*)(dst + A_LO_OFF + r * AST + c * 16) = nAl[i];
            }
            *(uint4*)(dst + B_HI_OFF + br * AST + bc_ * 16) = nBh;
            *(uint4*)(dst + B_LO_OFF + br * AST + bc_ * 16) = nBl;
        }
        __syncthreads();
    }

    // ---- epilogue ----
    #pragma unroll
    for (int mt = 0; mt < 2; mt++) {
        #pragma unroll
        for (int nt = 0; nt < 4; nt++) {
            const float* d = acc[mt][nt];
            int gr0  = (int)row0 + wm * 32 + mt * 16 + (lane >> 2);
            int gcol = n0 + wn * 32 + nt * 8 + (lane & 3) * 2;
            float b0 = (gcol < HQ) ? bias[gcol]     : 0.f;
            float b1 = (gcol < HQ) ? bias[gcol + 1] : 0.f;
            float v00 = d[0] + b0, v01 = d[1] + b1;
            float v10 = d[2] + b0, v11 = d[3] + b1;
            v00 = v00 > 0.f ? v00 : 0.f;
            v01 = v01 > 0.f ? v01 : 0.f;
            v10 = v10 > 0.f ? v10 : 0.f;
            v11 = v11 > 0.f ? v11 : 0.f;
            if (mode == 0) {
                float2 p0 = make_float2(v00, v01), p1 = make_float2(v10, v11);
                __nv_bfloat162 h0 = __float22bfloat162_rn(p0);
                __nv_bfloat162 h1v = __float22bfloat162_rn(p1);
                float2 l0 = make_float2(v00 - __bfloat162float(h0.x), v01 - __bfloat162float(h0.y));
                float2 l1 = make_float2(v10 - __bfloat162float(h1v.x), v11 - __bfloat162float(h1v.y));
                __nv_bfloat162 lo0 = __float22bfloat162_rn(l0);
                __nv_bfloat162 lo1 = __float22bfloat162_rn(l1);
                *(__nv_bfloat162*)&Ch[(long)gr0 * KP + gcol]       = h0;
                *(__nv_bfloat162*)&Cl[(long)gr0 * KP + gcol]       = lo0;
                *(__nv_bfloat162*)&Ch[(long)(gr0 + 8) * KP + gcol] = h1v;
                *(__nv_bfloat162*)&Cl[(long)(gr0 + 8) * KP + gcol] = lo1;
            } else if (gcol < HQ) {
                *(float2*)&Cf[(long)gr0 * HQ + gcol]       = make_float2(v00, v01);
                *(float2*)&Cf[(long)(gr0 + 8) * HQ + gcol] = make_float2(v10, v11);
            }
        }
    }
}

// ---------------------------------------------------------------------------
// out = fm * W_out[0] + h2 . W_out[1:] + b_out   (warp per row, float4)
// ---------------------------------------------------------------------------
__global__ __launch_bounds__(256)
void out_kernel(const float* __restrict__ Wout,
                const float* __restrict__ bout,
                float* __restrict__ out)
{
    __shared__ float sW[HQ];
    __shared__ float sw0, sb;
    int tid = threadIdx.x;
    for (int i = tid; i < HQ; i += 256) sW[i] = Wout[1 + i];
    if (tid == 0) { sw0 = Wout[0]; sb = bout[0]; }
    __syncthreads();

    int wid = tid >> 5, lane = tid & 31;
    int row = blockIdx.x * 8 + wid;
    const float4* h = (const float4*)(g_h2 + (long)row * HQ);
    float acc = 0.f;
    for (int j = lane; j < HQ / 4; j += 32) {
        float4 v = h[j];
        acc += v.x * sW[4 * j] + v.y * sW[4 * j + 1] + v.z * sW[4 * j + 2] + v.w * sW[4 * j + 3];
    }
    #pragma unroll
    for (int o = 16; o > 0; o >>= 1)
        acc += __shfl_down_sync(0xffffffffu, acc, o);
    if (lane == 0)
        out[row] = g_fm[row] * sw0 + acc + sb;
}

// ---------------------------------------------------------------------------
// Launch
// ---------------------------------------------------------------------------
extern "C" void kernel_launch(void* const* d_in, const int* in_sizes, int n_in,
                              void* d_out, int out_size)
{
    const float* cont = (const float*)d_in[0];
    const int*   cat  = (const int*)  d_in[1];
    const float* Wc   = (const float*)d_in[2];
    const float* bc   = (const float*)d_in[3];
    const float* emb1 = (const float*)d_in[4];
    const float* emb  = (const float*)d_in[5];
    const float* W1   = (const float*)d_in[6];
    const float* b1   = (const float*)d_in[7];
    const float* W2   = (const float*)d_in[8];
    const float* b2   = (const float*)d_in[9];
    const float* Wout = (const float*)d_in[10];
    const float* bout = (const float*)d_in[11];
    float* out = (float*)d_out;

    void *p;
    cudaGetSymbolAddress(&p, g_dnn_hi); __nv_bfloat16* dnn_hi = (__nv_bfloat16*)p;
    cudaGetSymbolAddress(&p, g_dnn_lo); __nv_bfloat16* dnn_lo = (__nv_bfloat16*)p;
    cudaGetSymbolAddress(&p, g_h1_hi);  __nv_bfloat16* h1_hi  = (__nv_bfloat16*)p;
    cudaGetSymbolAddress(&p, g_h1_lo);  __nv_bfloat16* h1_lo  = (__nv_bfloat16*)p;
    cudaGetSymbolAddress(&p, g_h2);     float*         h2     = (float*)p;
    cudaGetSymbolAddress(&p, g_w1t_hi); __nv_bfloat16* w1h    = (__nv_bfloat16*)p;
    cudaGetSymbolAddress(&p, g_w1t_lo); __nv_bfloat16* w1l    = (__nv_bfloat16*)p;
    cudaGetSymbolAddress(&p, g_w2t_hi); __nv_bfloat16* w2h    = (__nv_bfloat16*)p;
    cudaGetSymbolAddress(&p, g_w2t_lo); __nv_bfloat16* w2l    = (__nv_bfloat16*)p;

    static bool attr_set = false;
    if (!attr_set) {
        cudaFuncSetAttribute(gemm_mma_kernel,
                             cudaFuncAttributeMaxDynamicSharedMemorySize, SMEM_TOTAL);
        attr_set = true;
    }

    // weight prep (tiny)
    {
        int total = NPAD * KP;
        prep_w_kernel<<<(total + 255) / 256, 256>>>(W1, w1h, w1l, DNN_INQ, HQ);
        prep_w_kernel<<<(total + 255) / 256, 256>>>(W2, w2h, w2l, HQ, HQ);
    }
    // gather + FM + dnn_in (bf16 split)
    {
        dim3 blk(32, 8);
        gather_fm_kernel<<<BQ / 8, blk>>>(cont, cat, Wc, bc, emb1, emb);
    }
    // h1 = relu(dnn @ W1 + b1)
    {
        dim3 grd(NPAD / BN, BQ / BM);   // (7, 128)
        gemm_mma_kernel<<<grd, 256, SMEM_TOTAL>>>(dnn_hi, dnn_lo, w1h, w1l, b1, 0,
                                                  h1_hi, h1_lo, nullptr);
    }
    // h2 = relu(h1 @ W2 + b2)
    {
        dim3 grd(NPAD / BN, BQ / BM);
        gemm_mma_kernel<<<grd, 256, SMEM_TOTAL>>>(h1_hi, h1_lo, w2h, w2l, b2, 1,
                                                  nullptr, nullptr, h2);
    }
    // final
    out_kernel<<<BQ / 8, 256>>>(Wout, bout, out);
}